// round 7
// baseline (speedup 1.0000x reference)
#include <cuda_runtime.h>

#define D 64
#define NMAX 100032
#define EMAX 1600000
#define BM 96

// ---------------- device scratch (no allocations allowed) ----------------
__device__ __align__(16) float g_tmp[NMAX * D];   // act(h) + neighbor sums
__device__ __align__(16) float g_u[NMAX * D];     // GEMM1 output (pre inner-BN)
__device__ __align__(16) float g_v[NMAX * D];     // GEMM2 output (pre outer-BN)
__device__ double g_sumA[D], g_sqA[D], g_sumB[D], g_sqB[D];
__device__ int g_deg[NMAX];
__device__ int g_rowptr[NMAX + 1];
__device__ int g_cursor[NMAX];
__device__ int g_csr[EMAX];      // src per grouped position
__device__ int g_csrdst[EMAX];   // dst per grouped position

// ---------------- f32x2 helpers ----------------
__device__ __forceinline__ unsigned long long pack2(float x) {
    unsigned long long r;
    asm("mov.b64 %0, {%1, %1};" : "=l"(r) : "r"(__float_as_uint(x)));
    return r;
}
__device__ __forceinline__ void ffma2(unsigned long long& d,
                                      unsigned long long a, unsigned long long b) {
    asm("fma.rn.f32x2 %0, %1, %2, %0;" : "+l"(d) : "l"(a), "l"(b));
}
union Cvt2 { unsigned long long u; float2 f; };

// ---------------- CSR build ----------------
__global__ void zero_kernel(int n) {
    int idx = blockIdx.x * blockDim.x + threadIdx.x;
    if (idx < n) g_deg[idx] = 0;
}

__global__ void hist_kernel(const int* __restrict__ ei, int E) {
    int e = blockIdx.x * blockDim.x + threadIdx.x;
    if (e < E) atomicAdd(&g_deg[__ldg(&ei[E + e])], 1);
}

__global__ __launch_bounds__(1024) void scan_kernel(int n) {
    __shared__ int s[1024];
    int t = threadIdx.x;
    int chunk = (n + 1023) >> 10;
    int beg = t * chunk;
    int end = min(beg + chunk, n);
    int sum = 0;
    for (int i = beg; i < end; i++) sum += g_deg[i];
    s[t] = sum;
    __syncthreads();
    for (int off = 1; off < 1024; off <<= 1) {
        int x = (t >= off) ? s[t - off] : 0;
        __syncthreads();
        s[t] += x;
        __syncthreads();
    }
    int run = s[t] - sum;   // exclusive prefix
    for (int i = beg; i < end; i++) {
        g_rowptr[i] = run;
        g_cursor[i] = run;
        run += g_deg[i];
    }
    if (t == 1023) g_rowptr[n] = run;
}

__global__ void scatter_kernel(const int* __restrict__ ei, int E) {
    int e = blockIdx.x * blockDim.x + threadIdx.x;
    if (e >= E) return;
    int src = __ldg(&ei[e]);
    int dst = __ldg(&ei[E + e]);
    int pos = atomicAdd(&g_cursor[dst], 1);
    g_csr[pos] = src;
    g_csrdst[pos] = dst;
}

// ---------------- init: g_tmp = act(h); zero inner-BN accumulators ----------------
// act = relu(outerBN_{l-1}) when gamma != null (layer >= 1), identity otherwise.
__global__ __launch_bounds__(256) void init_tmp_kernel(
    const float* hsrc, const float* gamma, const float* beta,
    int n, double inv_n)
{
    __shared__ float sc_s[D], sh_s[D];
    int tid = threadIdx.x;
    int use_bn = (gamma != nullptr);
    if (!hsrc) hsrc = (const float*)g_v;
    if (tid < D) {
        if (use_bn) {
            double s = g_sumB[tid], q = g_sqB[tid];
            float mean = (float)(s * inv_n);
            float var = (float)(q * inv_n - (s * inv_n) * (s * inv_n));
            float sc = __ldg(&gamma[tid]) * rsqrtf(var + 1e-5f);
            sc_s[tid] = sc;
            sh_s[tid] = __ldg(&beta[tid]) - mean * sc;
        }
        g_sumA[tid] = 0.0;    // concurrent same-value stores, no readers yet
        g_sqA[tid] = 0.0;
    }
    __syncthreads();
    int idx = blockIdx.x * blockDim.x + tid;
    if (idx >= n * 16) return;
    int k4 = (idx & 15) * 4;
    float4 a = __ldg((const float4*)hsrc + idx);
    if (use_bn) {
        float4 s = *(const float4*)&sc_s[k4];
        float4 t = *(const float4*)&sh_s[k4];
        a.x = fmaxf(fmaf(a.x, s.x, t.x), 0.f);
        a.y = fmaxf(fmaf(a.y, s.y, t.y), 0.f);
        a.z = fmaxf(fmaf(a.z, s.z, t.z), 0.f);
        a.w = fmaxf(fmaf(a.w, s.w, t.w), 0.f);
    }
    *((float4*)g_tmp + idx) = a;
}

// ---------------- edge phase: segmented reduce over dst-grouped CSR ----------------
// block = 16 consecutive CSR positions x 16 channel-lanes (256 thr).
// Loads act(h[src]) coalesced, scan-merges same-dst runs in smem,
// one float4 RED per segment per channel-chunk.
__global__ __launch_bounds__(256) void edge_seg_kernel(
    const float* hsrc, const float* gamma, const float* beta,
    int E, double inv_n)
{
    __shared__ float val[16][68];
    __shared__ int sdst[16];
    __shared__ float sc_s[D], sh_s[D];
    int tid = threadIdx.x;
    int use_bn = (gamma != nullptr);
    if (!hsrc) hsrc = (const float*)g_v;
    if (use_bn && tid < D) {
        double s = g_sumB[tid], q = g_sqB[tid];
        float mean = (float)(s * inv_n);
        float var = (float)(q * inv_n - (s * inv_n) * (s * inv_n));
        float sc = __ldg(&gamma[tid]) * rsqrtf(var + 1e-5f);
        sc_s[tid] = sc;
        sh_s[tid] = __ldg(&beta[tid]) - mean * sc;
    }

    int e = tid >> 4;
    int k4 = (tid & 15) * 4;
    int pos = blockIdx.x * 16 + e;
    int dst = -1, src = 0;
    if (pos < E) { dst = __ldg(&g_csrdst[pos]); src = __ldg(&g_csr[pos]); }
    if ((tid & 15) == 0) sdst[e] = dst;

    float4 b = make_float4(0.f, 0.f, 0.f, 0.f);
    if (dst >= 0) b = __ldg((const float4*)(hsrc + (size_t)src * D + k4));
    __syncthreads();   // sc_s/sh_s + sdst visible
    if (dst >= 0 && use_bn) {
        float4 s = *(const float4*)&sc_s[k4];
        float4 t = *(const float4*)&sh_s[k4];
        b.x = fmaxf(fmaf(b.x, s.x, t.x), 0.f);
        b.y = fmaxf(fmaf(b.y, s.y, t.y), 0.f);
        b.z = fmaxf(fmaf(b.z, s.z, t.z), 0.f);
        b.w = fmaxf(fmaf(b.w, s.w, t.w), 0.f);
    }
    *(float4*)&val[e][k4] = b;
    __syncthreads();

    // segmented inclusive scan across the 16 entries (equality-guarded)
    #pragma unroll
    for (int step = 1; step < 16; step <<= 1) {
        bool add = (e >= step) && (sdst[e] == sdst[e - step]);
        float4 other = make_float4(0.f, 0.f, 0.f, 0.f);
        if (add) other = *(const float4*)&val[e - step][k4];
        __syncthreads();
        if (add) {
            float4 cur = *(float4*)&val[e][k4];
            cur.x += other.x; cur.y += other.y;
            cur.z += other.z; cur.w += other.w;
            *(float4*)&val[e][k4] = cur;
        }
        __syncthreads();
    }

    // segment tails emit one RED each
    if (dst >= 0 && (e == 15 || sdst[e + 1] != dst)) {
        atomicAdd((float4*)(g_tmp + (size_t)dst * D + k4), *(float4*)&val[e][k4]);
    }
}

// ---------------- GEMM1: u = g_tmp @ W1 + b1; stats -> sumA/sqA ----------------
__global__ __launch_bounds__(256) void gemm1_kernel(
    const float* __restrict__ Wall, const float* __restrict__ ball,
    int l, int n)
{
    __shared__ float As[BM][68];
    __shared__ float Ws[D][D];
    __shared__ float red[16][D];

    const float* W = Wall + (size_t)l * D * D;
    const float* bias = ball + (size_t)l * D;
    int tid = threadIdx.x;
    int row0 = blockIdx.x * BM;

    if (tid < D) { g_sumB[tid] = 0.0; g_sqB[tid] = 0.0; }

    #pragma unroll
    for (int i = tid; i < D * D / 4; i += 256)
        ((float4*)Ws)[i] = __ldg((const float4*)W + i);

    for (int i = tid; i < BM * 16; i += 256) {
        int r = i >> 4, k4 = (i & 15) * 4;
        int gr = row0 + r;
        float4 av = make_float4(0.f, 0.f, 0.f, 0.f);
        if (gr < n) av = *(const float4*)(g_tmp + (size_t)gr * D + k4);
        *(float4*)&As[r][k4] = av;
    }
    __syncthreads();

    int tx = tid & 15, ty = tid >> 4;
    int c0 = tx * 4;
    unsigned long long acc01[6], acc23[6];
    #pragma unroll
    for (int i = 0; i < 6; i++) { acc01[i] = 0ull; acc23[i] = 0ull; }

    #pragma unroll
    for (int k = 0; k < D; k += 4) {
        ulonglong2 w0 = *(const ulonglong2*)&Ws[k + 0][c0];
        ulonglong2 w1 = *(const ulonglong2*)&Ws[k + 1][c0];
        ulonglong2 w2 = *(const ulonglong2*)&Ws[k + 2][c0];
        ulonglong2 w3 = *(const ulonglong2*)&Ws[k + 3][c0];
        #pragma unroll
        for (int i = 0; i < 6; i++) {
            float4 a = *(const float4*)&As[ty * 6 + i][k];
            unsigned long long px = pack2(a.x), py = pack2(a.y);
            unsigned long long pz = pack2(a.z), pw = pack2(a.w);
            ffma2(acc01[i], px, w0.x); ffma2(acc23[i], px, w0.y);
            ffma2(acc01[i], py, w1.x); ffma2(acc23[i], py, w1.y);
            ffma2(acc01[i], pz, w2.x); ffma2(acc23[i], pz, w2.y);
            ffma2(acc01[i], pw, w3.x); ffma2(acc23[i], pw, w3.y);
        }
    }

    float4 bv = *(const float4*)(bias + c0);
    float csum[4] = {0.f, 0.f, 0.f, 0.f};
    float csq[4]  = {0.f, 0.f, 0.f, 0.f};
    #pragma unroll
    for (int i = 0; i < 6; i++) {
        int gr = row0 + ty * 6 + i;
        if (gr < n) {
            Cvt2 c01, c23; c01.u = acc01[i]; c23.u = acc23[i];
            float4 o;
            o.x = c01.f.x + bv.x;
            o.y = c01.f.y + bv.y;
            o.z = c23.f.x + bv.z;
            o.w = c23.f.y + bv.w;
            *(float4*)(g_u + (size_t)gr * D + c0) = o;
            csum[0] += o.x; csq[0] += o.x * o.x;
            csum[1] += o.y; csq[1] += o.y * o.y;
            csum[2] += o.z; csq[2] += o.z * o.z;
            csum[3] += o.w; csq[3] += o.w * o.w;
        }
    }
    __syncthreads();
    #pragma unroll
    for (int c = 0; c < 4; c++) red[ty][c0 + c] = csum[c];
    __syncthreads();
    if (tid < D) {
        float s = 0.f;
        #pragma unroll
        for (int t = 0; t < 16; t++) s += red[t][tid];
        atomicAdd(&g_sumA[tid], (double)s);
    }
    __syncthreads();
    #pragma unroll
    for (int c = 0; c < 4; c++) red[ty][c0 + c] = csq[c];
    __syncthreads();
    if (tid < D) {
        float s = 0.f;
        #pragma unroll
        for (int t = 0; t < 16; t++) s += red[t][tid];
        atomicAdd(&g_sqA[tid], (double)s);
    }
}

// ---------------- GEMM2: v = relu(innerBN(u)) @ W2 + b2; stats -> sumB/sqB ----------------
__global__ __launch_bounds__(256) void gemm2_kernel(
    const float* __restrict__ Wall, const float* __restrict__ ball,
    const float* __restrict__ gamma, const float* __restrict__ beta,
    int l, int n, double inv_n)
{
    __shared__ float As[BM][68];
    __shared__ float Ws[D][D];
    __shared__ float red[16][D];
    __shared__ float sc_s[D], sh_s[D];

    const float* W = Wall + (size_t)l * D * D;
    const float* bias = ball + (size_t)l * D;
    int tid = threadIdx.x;
    int row0 = blockIdx.x * BM;

    if (tid < D) {
        double s = g_sumA[tid], q = g_sqA[tid];
        float mean = (float)(s * inv_n);
        float var = (float)(q * inv_n - (s * inv_n) * (s * inv_n));
        float sc = __ldg(&gamma[tid]) * rsqrtf(var + 1e-5f);
        sc_s[tid] = sc;
        sh_s[tid] = __ldg(&beta[tid]) - mean * sc;
    }

    #pragma unroll
    for (int i = tid; i < D * D / 4; i += 256)
        ((float4*)Ws)[i] = __ldg((const float4*)W + i);
    __syncthreads();

    for (int i = tid; i < BM * 16; i += 256) {
        int r = i >> 4, k4 = (i & 15) * 4;
        int gr = row0 + r;
        float4 av = make_float4(0.f, 0.f, 0.f, 0.f);
        if (gr < n) {
            av = *(const float4*)(g_u + (size_t)gr * D + k4);
            float4 s = *(const float4*)&sc_s[k4];
            float4 t = *(const float4*)&sh_s[k4];
            av.x = fmaxf(fmaf(av.x, s.x, t.x), 0.f);
            av.y = fmaxf(fmaf(av.y, s.y, t.y), 0.f);
            av.z = fmaxf(fmaf(av.z, s.z, t.z), 0.f);
            av.w = fmaxf(fmaf(av.w, s.w, t.w), 0.f);
        }
        *(float4*)&As[r][k4] = av;
    }
    __syncthreads();

    int tx = tid & 15, ty = tid >> 4;
    int c0 = tx * 4;
    unsigned long long acc01[6], acc23[6];
    #pragma unroll
    for (int i = 0; i < 6; i++) { acc01[i] = 0ull; acc23[i] = 0ull; }

    #pragma unroll
    for (int k = 0; k < D; k += 4) {
        ulonglong2 w0 = *(const ulonglong2*)&Ws[k + 0][c0];
        ulonglong2 w1 = *(const ulonglong2*)&Ws[k + 1][c0];
        ulonglong2 w2 = *(const ulonglong2*)&Ws[k + 2][c0];
        ulonglong2 w3 = *(const ulonglong2*)&Ws[k + 3][c0];
        #pragma unroll
        for (int i = 0; i < 6; i++) {
            float4 a = *(const float4*)&As[ty * 6 + i][k];
            unsigned long long px = pack2(a.x), py = pack2(a.y);
            unsigned long long pz = pack2(a.z), pw = pack2(a.w);
            ffma2(acc01[i], px, w0.x); ffma2(acc23[i], px, w0.y);
            ffma2(acc01[i], py, w1.x); ffma2(acc23[i], py, w1.y);
            ffma2(acc01[i], pz, w2.x); ffma2(acc23[i], pz, w2.y);
            ffma2(acc01[i], pw, w3.x); ffma2(acc23[i], pw, w3.y);
        }
    }

    float4 bv = *(const float4*)(bias + c0);
    float csum[4] = {0.f, 0.f, 0.f, 0.f};
    float csq[4]  = {0.f, 0.f, 0.f, 0.f};
    #pragma unroll
    for (int i = 0; i < 6; i++) {
        int gr = row0 + ty * 6 + i;
        if (gr < n) {
            Cvt2 c01, c23; c01.u = acc01[i]; c23.u = acc23[i];
            float4 o;
            o.x = c01.f.x + bv.x;
            o.y = c01.f.y + bv.y;
            o.z = c23.f.x + bv.z;
            o.w = c23.f.y + bv.w;
            *(float4*)(g_v + (size_t)gr * D + c0) = o;
            csum[0] += o.x; csq[0] += o.x * o.x;
            csum[1] += o.y; csq[1] += o.y * o.y;
            csum[2] += o.z; csq[2] += o.z * o.z;
            csum[3] += o.w; csq[3] += o.w * o.w;
        }
    }
    __syncthreads();
    #pragma unroll
    for (int c = 0; c < 4; c++) red[ty][c0 + c] = csum[c];
    __syncthreads();
    if (tid < D) {
        float s = 0.f;
        #pragma unroll
        for (int t = 0; t < 16; t++) s += red[t][tid];
        atomicAdd(&g_sumB[tid], (double)s);
    }
    __syncthreads();
    #pragma unroll
    for (int c = 0; c < 4; c++) red[ty][c0 + c] = csq[c];
    __syncthreads();
    if (tid < D) {
        float s = 0.f;
        #pragma unroll
        for (int t = 0; t < 16; t++) s += red[t][tid];
        atomicAdd(&g_sqB[tid], (double)s);
    }
}

// ---------------- finalize: outer BN (no relu) -> out[N*D] + gathered out[K*D] ----------------
__global__ void finalize_kernel(const int* __restrict__ bi,
                                const float* __restrict__ gamma,
                                const float* __restrict__ beta,
                                float* __restrict__ out, int n, int K, double inv_n) {
    __shared__ float sc_s[D], sh_s[D];
    int tid = threadIdx.x;
    if (tid < D) {
        double s = g_sumB[tid], q = g_sqB[tid];
        float mean = (float)(s * inv_n);
        float var = (float)(q * inv_n - (s * inv_n) * (s * inv_n));
        float sc = __ldg(&gamma[tid]) * rsqrtf(var + 1e-5f);
        sc_s[tid] = sc;
        sh_s[tid] = __ldg(&beta[tid]) - mean * sc;
    }
    __syncthreads();
    int idx = blockIdx.x * blockDim.x + tid;
    int total = (n + K) * 16;
    if (idx >= total) return;
    int q4 = (idx & 15) * 4;
    int item = idx >> 4;
    int row;
    size_t opos;
    if (item < n) { row = item; opos = (size_t)item * D + q4; }
    else {
        int k = item - n;
        row = __ldg(&bi[k]);
        opos = (size_t)n * D + (size_t)k * D + q4;
    }
    float4 a = *(const float4*)&g_v[(size_t)row * D + q4];
    float4 s = *(const float4*)&sc_s[q4];
    float4 t = *(const float4*)&sh_s[q4];
    float4 o;
    o.x = fmaf(a.x, s.x, t.x);
    o.y = fmaf(a.y, s.y, t.y);
    o.z = fmaf(a.z, s.z, t.z);
    o.w = fmaf(a.w, s.w, t.w);
    *(float4*)&out[opos] = o;
}

extern "C" void kernel_launch(void* const* d_in, const int* in_sizes, int n_in,
                              void* d_out, int out_size) {
    const float* x   = (const float*)d_in[0];
    const int*   ei  = (const int*)d_in[1];
    const int*   bi  = (const int*)d_in[2];
    const float* W1  = (const float*)d_in[3];
    const float* b1  = (const float*)d_in[4];
    const float* g1  = (const float*)d_in[5];
    const float* be1 = (const float*)d_in[6];
    const float* W2  = (const float*)d_in[7];
    const float* b2  = (const float*)d_in[8];
    const float* g2  = (const float*)d_in[9];
    const float* be2 = (const float*)d_in[10];
    float* out = (float*)d_out;

    int n = in_sizes[0] / D;
    int E = in_sizes[1] / 2;
    int K = in_sizes[2];
    int L = in_sizes[3] / (D * D);

    int gN    = (n + 255) / 256;
    int gE    = (E + 255) / 256;
    int gInit = (n * 16 + 255) / 256;
    int gSeg  = (E + 15) / 16;
    int gGemm = (n + BM - 1) / BM;
    int gFin  = ((n + K) * 16 + 255) / 256;
    double inv_n = 1.0 / (double)n;

    zero_kernel<<<gN, 256>>>(n);
    hist_kernel<<<gE, 256>>>(ei, E);
    scan_kernel<<<1, 1024>>>(n);
    scatter_kernel<<<gE, 256>>>(ei, E);

    for (int l = 0; l < L; l++) {
        const float* gprev  = (l == 0) ? nullptr : g2 + (size_t)(l - 1) * D;
        const float* beprev = (l == 0) ? nullptr : be2 + (size_t)(l - 1) * D;
        const float* hsrc   = (l == 0) ? x : nullptr;   // null -> g_v inside kernels
        init_tmp_kernel<<<gInit, 256>>>(hsrc, gprev, beprev, n, inv_n);
        edge_seg_kernel<<<gSeg, 256>>>(hsrc, gprev, beprev, E, inv_n);
        gemm1_kernel<<<gGemm, 256>>>(W1, b1, l, n);
        gemm2_kernel<<<gGemm, 256>>>(W2, b2, g1 + (size_t)l * D, be1 + (size_t)l * D, l, n, inv_n);
    }
    finalize_kernel<<<gFin, 256>>>(bi, g2 + (size_t)(L - 1) * D, be2 + (size_t)(L - 1) * D, out, n, K, inv_n);
}

// round 8
// speedup vs baseline: 1.6840x; 1.6840x over previous
#include <cuda_runtime.h>

#define D 64
#define NMAX 100032
#define BM 96

// ---------------- device scratch (no allocations allowed) ----------------
__device__ __align__(16) float g_tmp[NMAX * D];   // act(h) + neighbor sums (GEMM1 input)
__device__ __align__(16) float g_u[NMAX * D];     // GEMM1 output (pre inner-BN)
__device__ __align__(16) float g_v[NMAX * D];     // GEMM2 output (pre outer-BN)
__device__ double g_sumA[D], g_sqA[D], g_sumB[D], g_sqB[D];

// compute BN scale/shift from double accumulators into shared arrays.
// call with tid < D lanes; caller must __syncthreads() afterwards.
__device__ __forceinline__ void bn_coeffs(int tid, const double* sum, const double* sq,
                                          const float* gamma, const float* beta,
                                          double inv_n, float* sc_s, float* sh_s) {
    if (tid < D) {
        double s = sum[tid], q = sq[tid];
        float mean = (float)(s * inv_n);
        float var = (float)(q * inv_n - (s * inv_n) * (s * inv_n));
        float sc = __ldg(&gamma[tid]) * rsqrtf(var + 1e-5f);
        sc_s[tid] = sc;
        sh_s[tid] = __ldg(&beta[tid]) - mean * sc;
    }
}

// ---------------- init: g_tmp = act(h); zero inner-BN accumulators ----------------
// act = relu(outerBN_{l-1}) when gamma != null (layer >= 1), identity otherwise.
__global__ __launch_bounds__(256) void init_tmp_kernel(
    const float* hsrc, const float* gamma, const float* beta,
    int n, double inv_n)
{
    __shared__ float sc_s[D], sh_s[D];
    int tid = threadIdx.x;
    int use_bn = (gamma != nullptr);
    if (!hsrc) hsrc = (const float*)g_v;
    if (use_bn) bn_coeffs(tid, g_sumB, g_sqB, gamma, beta, inv_n, sc_s, sh_s);
    if (tid < D) { g_sumA[tid] = 0.0; g_sqA[tid] = 0.0; }   // no readers until gemm1 done
    __syncthreads();
    int idx = blockIdx.x * blockDim.x + tid;
    if (idx >= n * 16) return;
    int k4 = (idx & 15) * 4;
    float4 a = __ldg((const float4*)hsrc + idx);
    if (use_bn) {
        float4 s = *(const float4*)&sc_s[k4];
        float4 t = *(const float4*)&sh_s[k4];
        a.x = fmaxf(fmaf(a.x, s.x, t.x), 0.f);
        a.y = fmaxf(fmaf(a.y, s.y, t.y), 0.f);
        a.z = fmaxf(fmaf(a.z, s.z, t.z), 0.f);
        a.w = fmaxf(fmaf(a.w, s.w, t.w), 0.f);
    }
    *((float4*)g_tmp + idx) = a;
}

// ---------------- edge phase: g_tmp[dst] += act(h[src]) (16 lanes/edge) ----------------
__global__ __launch_bounds__(256) void edge_kernel(
    const float* hsrc, const int* __restrict__ ei,
    const float* gamma, const float* beta,
    int E, double inv_n)
{
    __shared__ float sc_s[D], sh_s[D];
    int tid = threadIdx.x;
    int use_bn = (gamma != nullptr);
    if (!hsrc) hsrc = (const float*)g_v;
    if (use_bn) bn_coeffs(tid, g_sumB, g_sqB, gamma, beta, inv_n, sc_s, sh_s);
    __syncthreads();

    int idx = blockIdx.x * blockDim.x + tid;
    if (idx >= E * 16) return;
    int e = idx >> 4;
    int k4 = (idx & 15) * 4;
    int s = __ldg(&ei[e]);
    int d = __ldg(&ei[E + e]);
    float4 a = __ldg((const float4*)(hsrc + (size_t)s * D + k4));
    if (use_bn) {
        float4 sv = *(const float4*)&sc_s[k4];
        float4 tv = *(const float4*)&sh_s[k4];
        a.x = fmaxf(fmaf(a.x, sv.x, tv.x), 0.f);
        a.y = fmaxf(fmaf(a.y, sv.y, tv.y), 0.f);
        a.z = fmaxf(fmaf(a.z, sv.z, tv.z), 0.f);
        a.w = fmaxf(fmaf(a.w, sv.w, tv.w), 0.f);
    }
    atomicAdd((float4*)(g_tmp + (size_t)d * D + k4), a);
}

// ---------------- GEMM1: u = g_tmp @ W1 + b1; stats -> sumA/sqA ----------------
__global__ __launch_bounds__(256) void gemm1_kernel(
    const float* __restrict__ Wall, const float* __restrict__ ball,
    int l, int n)
{
    __shared__ float As[BM][68];
    __shared__ float Ws[D][D];
    __shared__ float red[16][D];

    const float* W = Wall + (size_t)l * D * D;
    const float* bias = ball + (size_t)l * D;
    int tid = threadIdx.x;
    int row0 = blockIdx.x * BM;

    // zero outer-BN accumulators (no readers until gemm2 completes; same-value stores safe)
    if (tid < D) { g_sumB[tid] = 0.0; g_sqB[tid] = 0.0; }

    #pragma unroll
    for (int i = tid; i < D * D / 4; i += 256)
        ((float4*)Ws)[i] = __ldg((const float4*)W + i);

    for (int i = tid; i < BM * 16; i += 256) {
        int r = i >> 4, k4 = (i & 15) * 4;
        int gr = row0 + r;
        float4 av = make_float4(0.f, 0.f, 0.f, 0.f);
        if (gr < n) av = *(const float4*)(g_tmp + (size_t)gr * D + k4);
        *(float4*)&As[r][k4] = av;
    }
    __syncthreads();

    int tx = tid & 15, ty = tid >> 4;
    int c0 = tx * 4;
    float acc[6][4];
    #pragma unroll
    for (int i = 0; i < 6; i++)
        #pragma unroll
        for (int c = 0; c < 4; c++) acc[i][c] = 0.f;

    #pragma unroll
    for (int k = 0; k < D; k += 4) {
        float4 w0 = *(const float4*)&Ws[k + 0][c0];
        float4 w1 = *(const float4*)&Ws[k + 1][c0];
        float4 w2 = *(const float4*)&Ws[k + 2][c0];
        float4 w3 = *(const float4*)&Ws[k + 3][c0];
        #pragma unroll
        for (int i = 0; i < 6; i++) {
            float4 a = *(const float4*)&As[ty * 6 + i][k];
            acc[i][0] = fmaf(a.x, w0.x, fmaf(a.y, w1.x, fmaf(a.z, w2.x, fmaf(a.w, w3.x, acc[i][0]))));
            acc[i][1] = fmaf(a.x, w0.y, fmaf(a.y, w1.y, fmaf(a.z, w2.y, fmaf(a.w, w3.y, acc[i][1]))));
            acc[i][2] = fmaf(a.x, w0.z, fmaf(a.y, w1.z, fmaf(a.z, w2.z, fmaf(a.w, w3.z, acc[i][2]))));
            acc[i][3] = fmaf(a.x, w0.w, fmaf(a.y, w1.w, fmaf(a.z, w2.w, fmaf(a.w, w3.w, acc[i][3]))));
        }
    }

    float4 bv = *(const float4*)(bias + c0);
    float csum[4] = {0.f, 0.f, 0.f, 0.f};
    float csq[4]  = {0.f, 0.f, 0.f, 0.f};
    #pragma unroll
    for (int i = 0; i < 6; i++) {
        int gr = row0 + ty * 6 + i;
        if (gr < n) {
            float4 o;
            o.x = acc[i][0] + bv.x;
            o.y = acc[i][1] + bv.y;
            o.z = acc[i][2] + bv.z;
            o.w = acc[i][3] + bv.w;
            *(float4*)(g_u + (size_t)gr * D + c0) = o;
            csum[0] += o.x; csq[0] += o.x * o.x;
            csum[1] += o.y; csq[1] += o.y * o.y;
            csum[2] += o.z; csq[2] += o.z * o.z;
            csum[3] += o.w; csq[3] += o.w * o.w;
        }
    }
    __syncthreads();
    #pragma unroll
    for (int c = 0; c < 4; c++) red[ty][c0 + c] = csum[c];
    __syncthreads();
    if (tid < D) {
        float s = 0.f;
        #pragma unroll
        for (int t = 0; t < 16; t++) s += red[t][tid];
        atomicAdd(&g_sumA[tid], (double)s);
    }
    __syncthreads();
    #pragma unroll
    for (int c = 0; c < 4; c++) red[ty][c0 + c] = csq[c];
    __syncthreads();
    if (tid < D) {
        float s = 0.f;
        #pragma unroll
        for (int t = 0; t < 16; t++) s += red[t][tid];
        atomicAdd(&g_sqA[tid], (double)s);
    }
}

// ---------------- GEMM2: v = relu(innerBN(u)) @ W2 + b2; stats -> sumB/sqB ----------------
__global__ __launch_bounds__(256) void gemm2_kernel(
    const float* __restrict__ Wall, const float* __restrict__ ball,
    const float* __restrict__ gamma, const float* __restrict__ beta,
    int l, int n, double inv_n)
{
    __shared__ float As[BM][68];
    __shared__ float Ws[D][D];
    __shared__ float red[16][D];
    __shared__ float sc_s[D], sh_s[D];

    const float* W = Wall + (size_t)l * D * D;
    const float* bias = ball + (size_t)l * D;
    int tid = threadIdx.x;
    int row0 = blockIdx.x * BM;

    bn_coeffs(tid, g_sumA, g_sqA, gamma, beta, inv_n, sc_s, sh_s);

    #pragma unroll
    for (int i = tid; i < D * D / 4; i += 256)
        ((float4*)Ws)[i] = __ldg((const float4*)W + i);
    __syncthreads();

    for (int i = tid; i < BM * 16; i += 256) {
        int r = i >> 4, k4 = (i & 15) * 4;
        int gr = row0 + r;
        float4 av = make_float4(0.f, 0.f, 0.f, 0.f);
        if (gr < n) {
            av = *(const float4*)(g_u + (size_t)gr * D + k4);
            float4 s = *(const float4*)&sc_s[k4];
            float4 t = *(const float4*)&sh_s[k4];
            av.x = fmaxf(fmaf(av.x, s.x, t.x), 0.f);
            av.y = fmaxf(fmaf(av.y, s.y, t.y), 0.f);
            av.z = fmaxf(fmaf(av.z, s.z, t.z), 0.f);
            av.w = fmaxf(fmaf(av.w, s.w, t.w), 0.f);
        }
        *(float4*)&As[r][k4] = av;
    }
    __syncthreads();

    int tx = tid & 15, ty = tid >> 4;
    int c0 = tx * 4;
    float acc[6][4];
    #pragma unroll
    for (int i = 0; i < 6; i++)
        #pragma unroll
        for (int c = 0; c < 4; c++) acc[i][c] = 0.f;

    #pragma unroll
    for (int k = 0; k < D; k += 4) {
        float4 w0 = *(const float4*)&Ws[k + 0][c0];
        float4 w1 = *(const float4*)&Ws[k + 1][c0];
        float4 w2 = *(const float4*)&Ws[k + 2][c0];
        float4 w3 = *(const float4*)&Ws[k + 3][c0];
        #pragma unroll
        for (int i = 0; i < 6; i++) {
            float4 a = *(const float4*)&As[ty * 6 + i][k];
            acc[i][0] = fmaf(a.x, w0.x, fmaf(a.y, w1.x, fmaf(a.z, w2.x, fmaf(a.w, w3.x, acc[i][0]))));
            acc[i][1] = fmaf(a.x, w0.y, fmaf(a.y, w1.y, fmaf(a.z, w2.y, fmaf(a.w, w3.y, acc[i][1]))));
            acc[i][2] = fmaf(a.x, w0.z, fmaf(a.y, w1.z, fmaf(a.z, w2.z, fmaf(a.w, w3.z, acc[i][2]))));
            acc[i][3] = fmaf(a.x, w0.w, fmaf(a.y, w1.w, fmaf(a.z, w2.w, fmaf(a.w, w3.w, acc[i][3]))));
        }
    }

    float4 bv = *(const float4*)(bias + c0);
    float csum[4] = {0.f, 0.f, 0.f, 0.f};
    float csq[4]  = {0.f, 0.f, 0.f, 0.f};
    #pragma unroll
    for (int i = 0; i < 6; i++) {
        int gr = row0 + ty * 6 + i;
        if (gr < n) {
            float4 o;
            o.x = acc[i][0] + bv.x;
            o.y = acc[i][1] + bv.y;
            o.z = acc[i][2] + bv.z;
            o.w = acc[i][3] + bv.w;
            *(float4*)(g_v + (size_t)gr * D + c0) = o;
            csum[0] += o.x; csq[0] += o.x * o.x;
            csum[1] += o.y; csq[1] += o.y * o.y;
            csum[2] += o.z; csq[2] += o.z * o.z;
            csum[3] += o.w; csq[3] += o.w * o.w;
        }
    }
    __syncthreads();
    #pragma unroll
    for (int c = 0; c < 4; c++) red[ty][c0 + c] = csum[c];
    __syncthreads();
    if (tid < D) {
        float s = 0.f;
        #pragma unroll
        for (int t = 0; t < 16; t++) s += red[t][tid];
        atomicAdd(&g_sumB[tid], (double)s);
    }
    __syncthreads();
    #pragma unroll
    for (int c = 0; c < 4; c++) red[ty][c0 + c] = csq[c];
    __syncthreads();
    if (tid < D) {
        float s = 0.f;
        #pragma unroll
        for (int t = 0; t < 16; t++) s += red[t][tid];
        atomicAdd(&g_sqB[tid], (double)s);
    }
}

// ---------------- finalize: outer BN (no relu) -> out[N*D] + gathered out[K*D] ----------------
__global__ void finalize_kernel(const int* __restrict__ bi,
                                const float* __restrict__ gamma,
                                const float* __restrict__ beta,
                                float* __restrict__ out, int n, int K, double inv_n) {
    __shared__ float sc_s[D], sh_s[D];
    int tid = threadIdx.x;
    bn_coeffs(tid, g_sumB, g_sqB, gamma, beta, inv_n, sc_s, sh_s);
    __syncthreads();
    int idx = blockIdx.x * blockDim.x + tid;
    int total = (n + K) * 16;
    if (idx >= total) return;
    int q4 = (idx & 15) * 4;
    int item = idx >> 4;
    int row;
    size_t opos;
    if (item < n) { row = item; opos = (size_t)item * D + q4; }
    else {
        int k = item - n;
        row = __ldg(&bi[k]);
        opos = (size_t)n * D + (size_t)k * D + q4;
    }
    float4 a = *(const float4*)&g_v[(size_t)row * D + q4];
    float4 s = *(const float4*)&sc_s[q4];
    float4 t = *(const float4*)&sh_s[q4];
    float4 o;
    o.x = fmaf(a.x, s.x, t.x);
    o.y = fmaf(a.y, s.y, t.y);
    o.z = fmaf(a.z, s.z, t.z);
    o.w = fmaf(a.w, s.w, t.w);
    *(float4*)&out[opos] = o;
}

extern "C" void kernel_launch(void* const* d_in, const int* in_sizes, int n_in,
                              void* d_out, int out_size) {
    const float* x   = (const float*)d_in[0];
    const int*   ei  = (const int*)d_in[1];
    const int*   bi  = (const int*)d_in[2];
    const float* W1  = (const float*)d_in[3];
    const float* b1  = (const float*)d_in[4];
    const float* g1  = (const float*)d_in[5];
    const float* be1 = (const float*)d_in[6];
    const float* W2  = (const float*)d_in[7];
    const float* b2  = (const float*)d_in[8];
    const float* g2  = (const float*)d_in[9];
    const float* be2 = (const float*)d_in[10];
    float* out = (float*)d_out;

    int n = in_sizes[0] / D;
    int E = in_sizes[1] / 2;
    int K = in_sizes[2];
    int L = in_sizes[3] / (D * D);

    int gInit = (n * 16 + 255) / 256;
    int gEdge = (E * 16 + 255) / 256;
    int gGemm = (n + BM - 1) / BM;
    int gFin  = ((n + K) * 16 + 255) / 256;
    double inv_n = 1.0 / (double)n;

    for (int l = 0; l < L; l++) {
        const float* gprev  = (l == 0) ? nullptr : g2 + (size_t)(l - 1) * D;
        const float* beprev = (l == 0) ? nullptr : be2 + (size_t)(l - 1) * D;
        const float* hsrc   = (l == 0) ? x : nullptr;   // null -> g_v inside kernels
        init_tmp_kernel<<<gInit, 256>>>(hsrc, gprev, beprev, n, inv_n);
        edge_kernel<<<gEdge, 256>>>(hsrc, ei, gprev, beprev, E, inv_n);
        gemm1_kernel<<<gGemm, 256>>>(W1, b1, l, n);
        gemm2_kernel<<<gGemm, 256>>>(W2, b2, g1 + (size_t)l * D, be1 + (size_t)l * D, l, n, inv_n);
    }
    finalize_kernel<<<gFin, 256>>>(bi, g2 + (size_t)(L - 1) * D, be2 + (size_t)(L - 1) * D, out, n, K, inv_n);
}

// round 9
// speedup vs baseline: 2.3516x; 1.3964x over previous
#include <cuda_runtime.h>

#define D 64
#define NMAX 100032
#define BM 96

// ---------------- device scratch (no allocations allowed) ----------------
__device__ __align__(16) float g_tmp[NMAX * D];   // h + sum_neighbors (GEMM1 input)
__device__ __align__(16) float g_u[NMAX * D];     // GEMM1 output (pre inner-BN)
__device__ __align__(16) float g_v[NMAX * D];     // GEMM2 output (pre outer-BN)
__device__ double g_sumA[D], g_sqA[D], g_sumB[D], g_sqB[D];
__device__ __align__(16) float g_scA[D], g_shA[D];   // inner BN scale/shift
__device__ __align__(16) float g_scB[D], g_shB[D];   // outer BN scale/shift

// ---------------- f32x2 helpers (verified in R7) ----------------
__device__ __forceinline__ unsigned long long pack2(float x) {
    unsigned long long r;
    asm("mov.b64 %0, {%1, %1};" : "=l"(r) : "r"(__float_as_uint(x)));
    return r;
}
__device__ __forceinline__ void ffma2(unsigned long long& d,
                                      unsigned long long a, unsigned long long b) {
    asm("fma.rn.f32x2 %0, %1, %2, %0;" : "+l"(d) : "l"(a), "l"(b));
}
union Cvt2 { unsigned long long u; float2 f; };

// apply outer-BN(+ReLU) of the previous layer when reading h
__device__ __forceinline__ float4 act_prev(float4 a, int q4, int use_v) {
    if (use_v) {
        float4 s = *(const float4*)&g_scB[q4];
        float4 t = *(const float4*)&g_shB[q4];
        a.x = fmaxf(fmaf(a.x, s.x, t.x), 0.f);
        a.y = fmaxf(fmaf(a.y, s.y, t.y), 0.f);
        a.z = fmaxf(fmaf(a.z, s.z, t.z), 0.f);
        a.w = fmaxf(fmaf(a.w, s.w, t.w), 0.f);
    }
    return a;
}

// ---------------- tmp = act(h); zero inner-BN stat accumulators ----------------
__global__ void init_tmp_kernel(const float* __restrict__ x, int use_v, int n) {
    int idx = blockIdx.x * blockDim.x + threadIdx.x;
    if (blockIdx.x == 0 && threadIdx.x < D) {
        g_sumA[threadIdx.x] = 0.0;
        g_sqA[threadIdx.x] = 0.0;
    }
    if (idx >= n * 16) return;
    int q4 = (idx & 15) * 4;
    const float* h = use_v ? g_v : x;
    float4 a = __ldg((const float4*)(h) + idx);
    a = act_prev(a, q4, use_v);
    *((float4*)g_tmp + idx) = a;
}

// ---------------- tmp[dst] += act(h[src]) over all edges ----------------
__global__ void edge_kernel(const float* __restrict__ x,
                            const int* __restrict__ ei, int E, int use_v) {
    int idx = blockIdx.x * blockDim.x + threadIdx.x;
    if (idx >= E * 16) return;
    int e = idx >> 4;
    int q4 = (idx & 15) * 4;
    int s = __ldg(&ei[e]);
    int d = __ldg(&ei[E + e]);
    const float* h = use_v ? g_v : x;
    float4 a = __ldg((const float4*)(h + (size_t)s * D + q4));
    a = act_prev(a, q4, use_v);
    atomicAdd((float4*)(g_tmp + (size_t)d * D + q4), a);
}

// ---------------- fused GEMM + bias + BN-stat accumulation (FFMA2 core) ----------------
// which==0: u = tmp @ W + b,               stats -> sumA/sqA
// which==1: v = relu(bn_inner(u)) @ W + b, stats -> sumB/sqB
__global__ __launch_bounds__(256) void gemm_bn_kernel(
    const float* __restrict__ Wall, const float* __restrict__ ball,
    int l, int which, int n)
{
    __shared__ float As[BM][68];      // padded, float4-aligned
    __shared__ float Ws[D][D];
    __shared__ float red[16][D];

    const float* W = Wall + (size_t)l * D * D;
    const float* bias = ball + (size_t)l * D;
    const float* A = which ? g_u : g_tmp;
    float* out = which ? g_v : g_u;
    double* sum = which ? g_sumB : g_sumA;
    double* sq  = which ? g_sqB  : g_sqA;

    int tid = threadIdx.x;
    int row0 = blockIdx.x * BM;

    // load W tile (64x64)
    #pragma unroll
    for (int i = tid; i < D * D / 4; i += 256)
        ((float4*)Ws)[i] = __ldg((const float4*)W + i);

    // load A tile (BM x 64), applying inner BN + ReLU for GEMM2
    for (int i = tid; i < BM * 16; i += 256) {
        int r = i >> 4, k4 = (i & 15) * 4;
        int gr = row0 + r;
        float4 av = make_float4(0.f, 0.f, 0.f, 0.f);
        if (gr < n) av = __ldg((const float4*)(A + (size_t)gr * D + k4));
        if (which) {
            float4 s = *(const float4*)&g_scA[k4];
            float4 t = *(const float4*)&g_shA[k4];
            av.x = fmaxf(fmaf(av.x, s.x, t.x), 0.f);
            av.y = fmaxf(fmaf(av.y, s.y, t.y), 0.f);
            av.z = fmaxf(fmaf(av.z, s.z, t.z), 0.f);
            av.w = fmaxf(fmaf(av.w, s.w, t.w), 0.f);
        }
        *(float4*)&As[r][k4] = av;
    }
    __syncthreads();

    int tx = tid & 15, ty = tid >> 4;
    int c0 = tx * 4;
    unsigned long long acc01[6], acc23[6];
    #pragma unroll
    for (int i = 0; i < 6; i++) { acc01[i] = 0ull; acc23[i] = 0ull; }

    #pragma unroll
    for (int k = 0; k < D; k += 4) {
        ulonglong2 w0 = *(const ulonglong2*)&Ws[k + 0][c0];
        ulonglong2 w1 = *(const ulonglong2*)&Ws[k + 1][c0];
        ulonglong2 w2 = *(const ulonglong2*)&Ws[k + 2][c0];
        ulonglong2 w3 = *(const ulonglong2*)&Ws[k + 3][c0];
        #pragma unroll
        for (int i = 0; i < 6; i++) {
            float4 a = *(const float4*)&As[ty * 6 + i][k];
            unsigned long long px = pack2(a.x), py = pack2(a.y);
            unsigned long long pz = pack2(a.z), pw = pack2(a.w);
            ffma2(acc01[i], px, w0.x); ffma2(acc23[i], px, w0.y);
            ffma2(acc01[i], py, w1.x); ffma2(acc23[i], py, w1.y);
            ffma2(acc01[i], pz, w2.x); ffma2(acc23[i], pz, w2.y);
            ffma2(acc01[i], pw, w3.x); ffma2(acc23[i], pw, w3.y);
        }
    }

    float4 bv = *(const float4*)(bias + c0);
    float csum[4] = {0.f, 0.f, 0.f, 0.f};
    float csq[4]  = {0.f, 0.f, 0.f, 0.f};
    #pragma unroll
    for (int i = 0; i < 6; i++) {
        int gr = row0 + ty * 6 + i;
        if (gr < n) {
            Cvt2 c01, c23; c01.u = acc01[i]; c23.u = acc23[i];
            float4 o;
            o.x = c01.f.x + bv.x;
            o.y = c01.f.y + bv.y;
            o.z = c23.f.x + bv.z;
            o.w = c23.f.y + bv.w;
            *(float4*)(out + (size_t)gr * D + c0) = o;
            csum[0] += o.x; csq[0] += o.x * o.x;
            csum[1] += o.y; csq[1] += o.y * o.y;
            csum[2] += o.z; csq[2] += o.z * o.z;
            csum[3] += o.w; csq[3] += o.w * o.w;
        }
    }
    __syncthreads();
    #pragma unroll
    for (int c = 0; c < 4; c++) red[ty][c0 + c] = csum[c];
    __syncthreads();
    if (tid < D) {
        float s = 0.f;
        #pragma unroll
        for (int t = 0; t < 16; t++) s += red[t][tid];
        atomicAdd(&sum[tid], (double)s);
    }
    __syncthreads();
    #pragma unroll
    for (int c = 0; c < 4; c++) red[ty][c0 + c] = csq[c];
    __syncthreads();
    if (tid < D) {
        float s = 0.f;
        #pragma unroll
        for (int t = 0; t < 16; t++) s += red[t][tid];
        atomicAdd(&sq[tid], (double)s);
    }
}

// ---------------- finalize BN stats into scale/shift ----------------
__global__ void stats_kernel(const float* __restrict__ gamma,
                             const float* __restrict__ beta,
                             int which, double inv_n) {
    int c = threadIdx.x;
    double s, q;
    if (which == 0) { s = g_sumA[c]; q = g_sqA[c]; }
    else            { s = g_sumB[c]; q = g_sqB[c]; }
    float mean = (float)(s * inv_n);
    float var  = (float)(q * inv_n - (s * inv_n) * (s * inv_n));
    float sc = gamma[c] * rsqrtf(var + 1e-5f);
    float sh = beta[c] - mean * sc;
    if (which == 0) {
        g_scA[c] = sc; g_shA[c] = sh;
        g_sumB[c] = 0.0; g_sqB[c] = 0.0;   // zero outer-BN accumulators for GEMM2
    } else {
        g_scB[c] = sc; g_shB[c] = sh;
    }
}

// ---------------- write node_representation + node_select ----------------
__global__ void finalize_kernel(const int* __restrict__ bi,
                                float* __restrict__ out, int n, int K) {
    int idx = blockIdx.x * blockDim.x + threadIdx.x;
    int total = (n + K) * 16;
    if (idx >= total) return;
    int q4 = (idx & 15) * 4;
    int item = idx >> 4;
    int row;
    size_t opos;
    if (item < n) { row = item; opos = (size_t)item * D + q4; }
    else {
        int k = item - n;
        row = __ldg(&bi[k]);
        opos = (size_t)n * D + (size_t)k * D + q4;
    }
    float4 a = *(const float4*)&g_v[(size_t)row * D + q4];
    float4 s = *(const float4*)&g_scB[q4];
    float4 t = *(const float4*)&g_shB[q4];
    float4 o;
    o.x = fmaf(a.x, s.x, t.x);
    o.y = fmaf(a.y, s.y, t.y);
    o.z = fmaf(a.z, s.z, t.z);
    o.w = fmaf(a.w, s.w, t.w);
    *(float4*)&out[opos] = o;
}

extern "C" void kernel_launch(void* const* d_in, const int* in_sizes, int n_in,
                              void* d_out, int out_size) {
    const float* x   = (const float*)d_in[0];
    const int*   ei  = (const int*)d_in[1];
    const int*   bi  = (const int*)d_in[2];
    const float* W1  = (const float*)d_in[3];
    const float* b1  = (const float*)d_in[4];
    const float* g1  = (const float*)d_in[5];
    const float* be1 = (const float*)d_in[6];
    const float* W2  = (const float*)d_in[7];
    const float* b2  = (const float*)d_in[8];
    const float* g2  = (const float*)d_in[9];
    const float* be2 = (const float*)d_in[10];
    float* out = (float*)d_out;

    int n = in_sizes[0] / D;
    int E = in_sizes[1] / 2;
    int K = in_sizes[2];
    int L = in_sizes[3] / (D * D);

    int gInit = (n * 16 + 255) / 256;
    int gEdge = (E * 16 + 255) / 256;
    int gGemm = (n + BM - 1) / BM;
    int gFin  = ((n + K) * 16 + 255) / 256;
    double inv_n = 1.0 / (double)n;

    for (int l = 0; l < L; l++) {
        int use_v = (l > 0);
        init_tmp_kernel<<<gInit, 256>>>(x, use_v, n);
        edge_kernel<<<gEdge, 256>>>(x, ei, E, use_v);
        gemm_bn_kernel<<<gGemm, 256>>>(W1, b1, l, 0, n);
        stats_kernel<<<1, D>>>(g1 + (size_t)l * D, be1 + (size_t)l * D, 0, inv_n);
        gemm_bn_kernel<<<gGemm, 256>>>(W2, b2, l, 1, n);
        stats_kernel<<<1, D>>>(g2 + (size_t)l * D, be2 + (size_t)l * D, 1, inv_n);
    }
    finalize_kernel<<<gFin, 256>>>(bi, out, n, K);
}